// round 2
// baseline (speedup 1.0000x reference)
#include <cuda_runtime.h>
#include <cstddef>

#define D0    128
#define NGRP  64
#define NB    256
#define TTOT  2560

// 256 threads = 8 warps. Warp w owns tokens {w, w+8, w+16, ...} (up to 8),
// lane owns float4 d-chunk. Theta values live in REGISTERS across the softmax
// barrier -> no SMEM tile, ~3x less L1 traffic.
__global__ __launch_bounds__(256, 4)
void ragged_attn_kernel(const float* __restrict__ s_i,
                        const float* __restrict__ theta,
                        float* __restrict__ out)
{
    __shared__ float u_sh[64];
    __shared__ float e_sh[64];
    __shared__ float part[8 * D0];     // per-warp partial output
    __shared__ float inv_sh;

    const int bid = blockIdx.x;
    const int b   = bid >> 6;          // batch
    const int g   = bid & 63;          // group

    // sizes cycle 16,32,48,64; starts within each 160-token cycle: 0,16,48,96
    const int gm  = g & 3;
    const int nt  = (gm + 1) << 4;                                  // 16/32/48/64
    const int pre = (gm == 0) ? 0 : (gm == 1) ? 16 : (gm == 2) ? 48 : 96;
    const int t0  = (g >> 2) * 160 + pre;

    const int tid  = threadIdx.x;
    const int lane = tid & 31;
    const int w    = tid >> 5;

    // s_i[b] float4 for this lane's d-chunk
    const float4 sv = __ldg(reinterpret_cast<const float4*>(s_i + (size_t)b * D0) + lane);

    const float4* th4 = reinterpret_cast<const float4*>(theta + ((size_t)b * TTOT + t0) * D0);

    const int cnt = nt >> 3;           // tokens per warp: 2/4/6/8

    // ---------- Phase 1: load to registers (streaming), fused partial dots ----
    float4 v[8];
    #pragma unroll
    for (int k = 0; k < 8; k++) {
        if (k < cnt) {
            const int t = w + (k << 3);
            v[k] = __ldcs(th4 + t * 32 + lane);
        }
    }
    #pragma unroll
    for (int k = 0; k < 8; k++) {
        if (k < cnt) {
            float r = v[k].x * sv.x + v[k].y * sv.y + v[k].z * sv.z + v[k].w * sv.w;
            r += __shfl_xor_sync(0xffffffffu, r, 16);
            r += __shfl_xor_sync(0xffffffffu, r, 8);
            r += __shfl_xor_sync(0xffffffffu, r, 4);
            r += __shfl_xor_sync(0xffffffffu, r, 2);
            r += __shfl_xor_sync(0xffffffffu, r, 1);
            if (lane == 0) u_sh[w + (k << 3)] = r * (1.0f / 128.0f);  // / d0
        }
    }
    __syncthreads();

    // ---------- Phase 2: softmax over <=64 scores (warp 0) ---------------------
    if (tid < 32) {
        const float a0 = (tid      < nt) ? u_sh[tid]      : -3.4e38f;
        const float a1 = (tid + 32 < nt) ? u_sh[tid + 32] : -3.4e38f;
        float m = fmaxf(a0, a1);
        #pragma unroll
        for (int o = 16; o > 0; o >>= 1)
            m = fmaxf(m, __shfl_xor_sync(0xffffffffu, m, o));
        const float e0 = (tid      < nt) ? __expf(a0 - m) : 0.0f;
        const float e1 = (tid + 32 < nt) ? __expf(a1 - m) : 0.0f;
        e_sh[tid]      = e0;
        e_sh[tid + 32] = e1;
        float s = e0 + e1;
        #pragma unroll
        for (int o = 16; o > 0; o >>= 1)
            s += __shfl_xor_sync(0xffffffffu, s, o);
        if (tid == 0) inv_sh = 1.0f / s;
    }
    __syncthreads();

    // ---------- Phase 3: weighted sum from REGISTERS --------------------------
    float4 acc = make_float4(0.f, 0.f, 0.f, 0.f);
    #pragma unroll
    for (int k = 0; k < 8; k++) {
        if (k < cnt) {
            const float e = e_sh[w + (k << 3)];
            acc.x += e * v[k].x;
            acc.y += e * v[k].y;
            acc.z += e * v[k].z;
            acc.w += e * v[k].w;
        }
    }
    reinterpret_cast<float4*>(part)[w * 32 + lane] = acc;
    __syncthreads();

    // cross-warp reduction: 128 threads, one output dim each
    if (tid < D0) {
        float s = 0.f;
        #pragma unroll
        for (int ww = 0; ww < 8; ww++)
            s += part[ww * D0 + tid];
        out[((size_t)b * NGRP + g) * D0 + tid] = s * inv_sh;
    }
}

extern "C" void kernel_launch(void* const* d_in, const int* in_sizes, int n_in,
                              void* d_out, int out_size)
{
    const float* s_i   = (const float*)d_in[0];   // [256,128]
    const float* theta = (const float*)d_in[1];   // [256,2560,128]
    float* out = (float*)d_out;                   // [256,64,128]
    (void)in_sizes; (void)n_in; (void)out_size;
    ragged_attn_kernel<<<NB * NGRP, 256>>>(s_i, theta, out);
}

// round 3
// speedup vs baseline: 1.0443x; 1.0443x over previous
#include <cuda_runtime.h>
#include <cstdint>
#include <cstddef>

#define D0      128
#define NGRP    64
#define NB      256
#define TTOT    2560
#define NTILES  (NB * NGRP)          // 16384
#define GRID    456                  // 3 CTAs/SM x 152 SMs
#define THREADS 128

// ---------------- PTX helpers ----------------
__device__ __forceinline__ uint32_t smem_u32(const void* p) {
    return (uint32_t)__cvta_generic_to_shared(p);
}
__device__ __forceinline__ void mbar_init(uint32_t mbar, uint32_t cnt) {
    asm volatile("mbarrier.init.shared.b64 [%0], %1;" :: "r"(mbar), "r"(cnt) : "memory");
}
__device__ __forceinline__ void mbar_expect_tx(uint32_t mbar, uint32_t bytes) {
    asm volatile("mbarrier.arrive.expect_tx.shared.b64 _, [%0], %1;"
                 :: "r"(mbar), "r"(bytes) : "memory");
}
__device__ __forceinline__ void bulk_g2s(uint32_t dst, const void* src,
                                         uint32_t bytes, uint32_t mbar) {
    asm volatile("cp.async.bulk.shared::cluster.global.mbarrier::complete_tx::bytes "
                 "[%0], [%1], %2, [%3];"
                 :: "r"(dst), "l"(src), "r"(bytes), "r"(mbar) : "memory");
}
__device__ __forceinline__ void mbar_wait(uint32_t mbar, uint32_t parity) {
    asm volatile(
        "{\n\t.reg .pred P;\n"
        "WL%=:\n\t"
        "mbarrier.try_wait.parity.acquire.cta.shared::cta.b64 P, [%0], %1, 0x989680;\n\t"
        "@P bra WD%=;\n\t"
        "bra WL%=;\n"
        "WD%=:\n\t}"
        :: "r"(mbar), "r"(parity) : "memory");
}
__device__ __forceinline__ void fence_async() {
    asm volatile("fence.proxy.async.shared::cta;" ::: "memory");
}

// ---------------- tile geometry ----------------
// sizes cycle 16,32,48,64 (gm = g&3); start within 160-token cycle: gm*(gm+1)*8
struct TG { int b, g, nt; const float* src; uint32_t bytes; };
__device__ __forceinline__ TG geom(int id, const float* __restrict__ theta) {
    TG t;
    t.b = id >> 6; t.g = id & 63;
    const int gm = t.g & 3;
    t.nt = (gm + 1) << 4;
    const int t0 = (t.g >> 2) * 160 + gm * (gm + 1) * 8;
    t.src   = theta + ((size_t)t.b * TTOT + t0) * D0;
    t.bytes = (uint32_t)t.nt * D0 * 4u;
    return t;
}

extern __shared__ float dynbuf[];    // 2 x (64*128) floats = 64 KB

__global__ __launch_bounds__(THREADS, 3)
void ragged_attn_pipe(const float* __restrict__ s_i,
                      const float* __restrict__ theta,
                      float* __restrict__ out)
{
    __shared__ float u_sh[64];
    __shared__ float e_sh[64];
    __shared__ float inv_sh;
    __shared__ __align__(8) unsigned long long mbar_st[2];

    const int tid  = threadIdx.x;
    const int lane = tid & 31;
    const int w    = tid >> 5;

    const uint32_t mb[2]  = { smem_u32(&mbar_st[0]), smem_u32(&mbar_st[1]) };
    float* const   bufp[2] = { dynbuf, dynbuf + 64 * D0 };

    const int start = (int)(((long long)blockIdx.x       * NTILES) / GRID);
    const int end   = (int)(((long long)(blockIdx.x + 1) * NTILES) / GRID);

    if (tid == 0) { mbar_init(mb[0], 1); mbar_init(mb[1], 1); }
    __syncthreads();

    // prologue: kick off first tile
    if (tid == 0 && start < end) {
        const TG t = geom(start, theta);
        mbar_expect_tx(mb[0], t.bytes);
        bulk_g2s(smem_u32(bufp[0]), t.src, t.bytes, mb[0]);
    }

    uint32_t ph[2] = { 0, 0 };

    for (int i = start; i < end; i++) {
        const int j = (i - start) & 1;
        float* const buf = bufp[j];

        // issue prefetch of next tile into the other buffer (freed by the
        // __syncthreads at the end of the previous iteration)
        if (i + 1 < end && tid == 0) {
            const TG n = geom(i + 1, theta);
            fence_async();
            mbar_expect_tx(mb[j ^ 1], n.bytes);
            bulk_g2s(smem_u32(bufp[j ^ 1]), n.src, n.bytes, mb[j ^ 1]);
        }

        // wait for current tile's data
        mbar_wait(mb[j], ph[j]);
        ph[j] ^= 1;

        const TG t = geom(i, theta);
        const int nt = t.nt;

        // s_i[b] chunk for this lane (L2-resident, tiny)
        const float4 sv = __ldg(reinterpret_cast<const float4*>(s_i + (size_t)t.b * D0) + lane);
        const float4* const t4 = reinterpret_cast<const float4*>(buf);

        // ---- phase A: scores; warp w owns tokens w, w+4, ... (<=16) ----
        float r[16];
        #pragma unroll
        for (int k = 0; k < 16; k++) {
            const int tk = w + (k << 2);
            if (tk < nt) {
                const float4 v = t4[tk * 32 + lane];
                r[k] = v.x * sv.x + v.y * sv.y + v.z * sv.z + v.w * sv.w;
            }
        }
        #pragma unroll
        for (int k = 0; k < 16; k++) {
            const int tk = w + (k << 2);
            if (tk < nt) {
                float x = r[k];
                x += __shfl_xor_sync(0xffffffffu, x, 16);
                x += __shfl_xor_sync(0xffffffffu, x, 8);
                x += __shfl_xor_sync(0xffffffffu, x, 4);
                x += __shfl_xor_sync(0xffffffffu, x, 2);
                x += __shfl_xor_sync(0xffffffffu, x, 1);
                if (lane == 0) u_sh[tk] = x * (1.0f / 128.0f);   // / d0
            }
        }
        __syncthreads();

        // ---- phase B: softmax over <= 64 scores (warp 0) ----
        if (tid < 32) {
            const float a0 = (tid      < nt) ? u_sh[tid]      : -3.4e38f;
            const float a1 = (tid + 32 < nt) ? u_sh[tid + 32] : -3.4e38f;
            float m = fmaxf(a0, a1);
            #pragma unroll
            for (int o = 16; o > 0; o >>= 1)
                m = fmaxf(m, __shfl_xor_sync(0xffffffffu, m, o));
            const float e0 = (tid      < nt) ? __expf(a0 - m) : 0.0f;
            const float e1 = (tid + 32 < nt) ? __expf(a1 - m) : 0.0f;
            e_sh[tid]      = e0;
            e_sh[tid + 32] = e1;
            float s = e0 + e1;
            #pragma unroll
            for (int o = 16; o > 0; o >>= 1)
                s += __shfl_xor_sync(0xffffffffu, s, o);
            if (tid == 0) inv_sh = 1.0f / s;
        }
        __syncthreads();

        // ---- phase C: weighted sum, thread-per-d (conflict-free LDS) ----
        float acc0 = 0.0f, acc1 = 0.0f;
        const int d = tid;
        #pragma unroll 4
        for (int tt = 0; tt < nt; tt += 2) {
            acc0 += e_sh[tt]     * buf[tt * D0 + d];
            acc1 += e_sh[tt + 1] * buf[(tt + 1) * D0 + d];
        }
        out[((size_t)t.b * NGRP + t.g) * D0 + d] = (acc0 + acc1) * inv_sh;

        __syncthreads();   // buffer free for the prefetch issued next iteration
    }
}

extern "C" void kernel_launch(void* const* d_in, const int* in_sizes, int n_in,
                              void* d_out, int out_size)
{
    const float* s_i   = (const float*)d_in[0];   // [256,128]
    const float* theta = (const float*)d_in[1];   // [256,2560,128]
    float* out = (float*)d_out;                   // [256,64,128]
    (void)in_sizes; (void)n_in; (void)out_size;

    const size_t dyn = 2 * 64 * D0 * sizeof(float);   // 64 KB
    cudaFuncSetAttribute(ragged_attn_pipe,
                         cudaFuncAttributeMaxDynamicSharedMemorySize, (int)dyn);
    ragged_attn_pipe<<<GRID, THREADS, dyn>>>(s_i, theta, out);
}

// round 4
// speedup vs baseline: 1.2897x; 1.2351x over previous
#include <cuda_runtime.h>
#include <cstdint>
#include <cstddef>

#define D0      128
#define NGRP    64
#define NB      256
#define TTOT    2560
#define NTILES  (NB * NGRP)          // 16384
#define GRID    304                  // 2 CTAs/SM x 152 SMs
#define THREADS 128
#define STAGES  3

// ---------------- PTX helpers ----------------
__device__ __forceinline__ uint32_t smem_u32(const void* p) {
    return (uint32_t)__cvta_generic_to_shared(p);
}
__device__ __forceinline__ void mbar_init(uint32_t mbar, uint32_t cnt) {
    asm volatile("mbarrier.init.shared.b64 [%0], %1;" :: "r"(mbar), "r"(cnt) : "memory");
}
__device__ __forceinline__ void mbar_expect_tx(uint32_t mbar, uint32_t bytes) {
    asm volatile("mbarrier.arrive.expect_tx.shared.b64 _, [%0], %1;"
                 :: "r"(mbar), "r"(bytes) : "memory");
}
__device__ __forceinline__ void bulk_g2s(uint32_t dst, const void* src,
                                         uint32_t bytes, uint32_t mbar) {
    asm volatile("cp.async.bulk.shared::cluster.global.mbarrier::complete_tx::bytes "
                 "[%0], [%1], %2, [%3];"
                 :: "r"(dst), "l"(src), "r"(bytes), "r"(mbar) : "memory");
}
__device__ __forceinline__ void mbar_wait(uint32_t mbar, uint32_t parity) {
    asm volatile(
        "{\n\t.reg .pred P;\n"
        "WL%=:\n\t"
        "mbarrier.try_wait.parity.acquire.cta.shared::cta.b64 P, [%0], %1, 0x989680;\n\t"
        "@P bra WD%=;\n\t"
        "bra WL%=;\n"
        "WD%=:\n\t}"
        :: "r"(mbar), "r"(parity) : "memory");
}
__device__ __forceinline__ void fence_async() {
    asm volatile("fence.proxy.async.shared::cta;" ::: "memory");
}

// ---------------- tile geometry ----------------
// sizes cycle 16,32,48,64 (gm = g&3); start within 160-token cycle: gm*(gm+1)*8
struct TG { int b, g, nt; const float* src; uint32_t bytes; };
__device__ __forceinline__ TG geom(int id, const float* __restrict__ theta) {
    TG t;
    t.b = id >> 6; t.g = id & 63;
    const int gm = t.g & 3;
    t.nt = (gm + 1) << 4;
    const int t0 = (t.g >> 2) * 160 + gm * (gm + 1) * 8;
    t.src   = theta + ((size_t)t.b * TTOT + t0) * D0;
    t.bytes = (uint32_t)t.nt * D0 * 4u;
    return t;
}

extern __shared__ float dynbuf[];    // STAGES x (64*128) floats = 96 KB

__global__ __launch_bounds__(THREADS, 2)
void ragged_attn_pipe3(const float* __restrict__ s_i,
                       const float* __restrict__ theta,
                       float* __restrict__ out)
{
    __shared__ float u_sh[64];
    __shared__ float e_sh[64];
    __shared__ __align__(8) unsigned long long mbar_st[STAGES];

    const int tid  = threadIdx.x;
    const int lane = tid & 31;
    const int w    = tid >> 5;
    const int gid  = lane >> 3;      // 8-lane group within warp (0..3)
    const int sub  = lane & 7;       // lane within group

    uint32_t mb[STAGES];
    float*   bufp[STAGES];
    #pragma unroll
    for (int s = 0; s < STAGES; s++) {
        mb[s]   = smem_u32(&mbar_st[s]);
        bufp[s] = dynbuf + s * 64 * D0;
    }

    const int start = (int)(((long long)blockIdx.x       * NTILES) / GRID);
    const int end   = (int)(((long long)(blockIdx.x + 1) * NTILES) / GRID);

    if (tid == 0) {
        #pragma unroll
        for (int s = 0; s < STAGES; s++) mbar_init(mb[s], 1);
    }
    __syncthreads();

    // prologue: fill the pipe
    if (tid == 0) {
        #pragma unroll
        for (int s = 0; s < STAGES; s++) {
            if (start + s < end) {
                const TG t = geom(start + s, theta);
                mbar_expect_tx(mb[s], t.bytes);
                bulk_g2s(smem_u32(bufp[s]), t.src, t.bytes, mb[s]);
            }
        }
    }

    uint32_t ph[STAGES] = { 0, 0, 0 };
    int stg = 0;

    for (int i = start; i < end; i++) {
        float* const buf = bufp[stg];

        mbar_wait(mb[stg], ph[stg]);
        ph[stg] ^= 1;

        const TG t = geom(i, theta);
        const int nt = t.nt;

        // s_i chunks for this thread's 4 column-quarters (L1/L2-resident)
        const float4* const s4p = reinterpret_cast<const float4*>(s_i + (size_t)t.b * D0);
        float4 s0 = __ldg(s4p + sub);
        float4 s1 = __ldg(s4p + sub + 8);
        float4 s2 = __ldg(s4p + sub + 16);
        float4 s3 = __ldg(s4p + sub + 24);

        const float4* const t4 = reinterpret_cast<const float4*>(buf);

        // ---- phase A: 8-lane group per token; 16 tokens per pass ----
        const int passes = nt >> 4;              // 1..4
        #pragma unroll
        for (int p = 0; p < 4; p++) {
            if (p < passes) {
                const int tk = (p << 4) + (w << 2) + gid;
                const float4 v0 = t4[tk * 32 + sub];
                const float4 v1 = t4[tk * 32 + sub + 8];
                const float4 v2 = t4[tk * 32 + sub + 16];
                const float4 v3 = t4[tk * 32 + sub + 24];
                float x = v0.x*s0.x + v0.y*s0.y + v0.z*s0.z + v0.w*s0.w
                        + v1.x*s1.x + v1.y*s1.y + v1.z*s1.z + v1.w*s1.w
                        + v2.x*s2.x + v2.y*s2.y + v2.z*s2.z + v2.w*s2.w
                        + v3.x*s3.x + v3.y*s3.y + v3.z*s3.z + v3.w*s3.w;
                x += __shfl_xor_sync(0xffffffffu, x, 4);
                x += __shfl_xor_sync(0xffffffffu, x, 2);
                x += __shfl_xor_sync(0xffffffffu, x, 1);
                if (sub == 0) u_sh[tk] = x * (1.0f / 128.0f);    // / d0
            }
        }
        __syncthreads();

        // ---- phase B: softmax over <= 64 scores (warp 0); fold 1/denom in ----
        if (tid < 32) {
            const float a0 = (tid      < nt) ? u_sh[tid]      : -3.4e38f;
            const float a1 = (tid + 32 < nt) ? u_sh[tid + 32] : -3.4e38f;
            float m = fmaxf(a0, a1);
            #pragma unroll
            for (int o = 16; o > 0; o >>= 1)
                m = fmaxf(m, __shfl_xor_sync(0xffffffffu, m, o));
            const float e0 = (tid      < nt) ? __expf(a0 - m) : 0.0f;
            const float e1 = (tid + 32 < nt) ? __expf(a1 - m) : 0.0f;
            float sden = e0 + e1;
            #pragma unroll
            for (int o = 16; o > 0; o >>= 1)
                sden += __shfl_xor_sync(0xffffffffu, sden, o);
            const float inv = 1.0f / sden;
            e_sh[tid]      = e0 * inv;
            e_sh[tid + 32] = e1 * inv;
        }
        __syncthreads();

        // ---- phase C: weighted sum, thread-per-d (conflict-free) ----
        float acc0 = 0.0f, acc1 = 0.0f;
        const int d = tid;
        #pragma unroll 4
        for (int tt = 0; tt < nt; tt += 2) {
            acc0 += e_sh[tt]     * buf[tt * D0 + d];
            acc1 += e_sh[tt + 1] * buf[(tt + 1) * D0 + d];
        }
        out[((size_t)t.b * NGRP + t.g) * D0 + d] = acc0 + acc1;

        __syncthreads();   // all reads of buf done -> stage reusable

        if (tid == 0 && i + STAGES < end) {
            const TG n = geom(i + STAGES, theta);
            fence_async();
            mbar_expect_tx(mb[stg], n.bytes);
            bulk_g2s(smem_u32(bufp[stg]), n.src, n.bytes, mb[stg]);
        }

        stg = (stg + 1 == STAGES) ? 0 : stg + 1;
    }
}

extern "C" void kernel_launch(void* const* d_in, const int* in_sizes, int n_in,
                              void* d_out, int out_size)
{
    const float* s_i   = (const float*)d_in[0];   // [256,128]
    const float* theta = (const float*)d_in[1];   // [256,2560,128]
    float* out = (float*)d_out;                   // [256,64,128]
    (void)in_sizes; (void)n_in; (void)out_size;

    const size_t dyn = STAGES * 64 * D0 * sizeof(float);   // 96 KB
    cudaFuncSetAttribute(ragged_attn_pipe3,
                         cudaFuncAttributeMaxDynamicSharedMemorySize, (int)dyn);
    ragged_attn_pipe3<<<GRID, THREADS, dyn>>>(s_i, theta, out);
}

// round 6
// speedup vs baseline: 1.3304x; 1.0315x over previous
#include <cuda_runtime.h>
#include <cstdint>
#include <cstddef>

#define D0      128
#define NGRP    64
#define NB      256
#define TTOT    2560
#define NTILES  (NB * NGRP)     // 16384
#define NQUADS  (NTILES / 4)    // 4096
#define GRID    152             // 1 CTA per SM
#define THREADS 256             // warps 0..6 consumers, warp 7 producer
#define NCONS   7
#define STAGE_F (64 * D0)       // floats per stage (max tile 64x128 = 32 KB)

// ---------------- PTX helpers ----------------
__device__ __forceinline__ uint32_t smem_u32(const void* p) {
    return (uint32_t)__cvta_generic_to_shared(p);
}
__device__ __forceinline__ void mbar_init(uint32_t mbar, uint32_t cnt) {
    asm volatile("mbarrier.init.shared.b64 [%0], %1;" :: "r"(mbar), "r"(cnt) : "memory");
}
__device__ __forceinline__ void mbar_expect_tx(uint32_t mbar, uint32_t bytes) {
    asm volatile("mbarrier.arrive.expect_tx.shared.b64 _, [%0], %1;"
                 :: "r"(mbar), "r"(bytes) : "memory");
}
__device__ __forceinline__ void mbar_arrive(uint32_t mbar) {
    asm volatile("mbarrier.arrive.shared.b64 _, [%0];" :: "r"(mbar) : "memory");
}
__device__ __forceinline__ void bulk_g2s(uint32_t dst, const void* src,
                                         uint32_t bytes, uint32_t mbar) {
    asm volatile("cp.async.bulk.shared::cluster.global.mbarrier::complete_tx::bytes "
                 "[%0], [%1], %2, [%3];"
                 :: "r"(dst), "l"(src), "r"(bytes), "r"(mbar) : "memory");
}
// blocks until the phase with the given parity has completed
__device__ __forceinline__ void mbar_wait(uint32_t mbar, uint32_t parity) {
    asm volatile(
        "{\n\t.reg .pred P;\n"
        "WL%=:\n\t"
        "mbarrier.try_wait.parity.acquire.cta.shared::cta.b64 P, [%0], %1, 0x989680;\n\t"
        "@P bra WD%=;\n\t"
        "bra WL%=;\n"
        "WD%=:\n\t}"
        :: "r"(mbar), "r"(parity) : "memory");
}
__device__ __forceinline__ void fence_async() {
    asm volatile("fence.proxy.async.shared::cta;" ::: "memory");
}

extern __shared__ float dynbuf[];   // NCONS * 32 KB = 224 KB

__global__ __launch_bounds__(THREADS, 1)
void ragged_attn_ws2(const float* __restrict__ s_i,
                     const float* __restrict__ theta,
                     float* __restrict__ out)
{
    __shared__ __align__(8)  unsigned long long full_b[NCONS];
    __shared__ __align__(8)  unsigned long long empty_b[NCONS];
    __shared__ __align__(16) float scores[NCONS][64];   // scalar access only

    const int tid  = threadIdx.x;
    const int lane = tid & 31;
    const int w    = tid >> 5;

    // tile range for this CTA, aligned to the 4-tile size cycle
    const int qs    = (int)(((long long)blockIdx.x       * NQUADS) / GRID);
    const int qe    = (int)(((long long)(blockIdx.x + 1) * NQUADS) / GRID);
    const int start = qs * 4;
    const int n     = (qe - qs) * 4;

    if (tid == 0) {
        #pragma unroll
        for (int s = 0; s < NCONS; s++) {
            mbar_init(smem_u32(&full_b[s]), 1);
            mbar_init(smem_u32(&empty_b[s]), 1);
        }
    }
    __syncthreads();   // the only block barrier

    if (w == NCONS) {
        // ===== producer: warp 7 lane 0, fills stage s with tiles l = r*7+s =====
        if (lane == 0) {
            int l = 0;
            for (int r = 0; l < n; r++) {
                const uint32_t ewait = (r & 1) ^ 1;   // r=0 passes on fresh barrier
                for (int s = 0; s < NCONS && l < n; s++, l++) {
                    mbar_wait(smem_u32(&empty_b[s]), ewait);

                    const int id = start + l;
                    const int gm = id & 3;
                    const int nt = (gm + 1) << 4;
                    const int g  = id & 63;
                    const int t0 = (g >> 2) * 160 + gm * (gm + 1) * 8;
                    const float* src = theta + ((size_t)(id >> 6) * TTOT + t0) * D0;
                    const uint32_t bytes = (uint32_t)nt * D0 * 4u;
                    const uint32_t fb = smem_u32(&full_b[s]);

                    fence_async();
                    mbar_expect_tx(fb, bytes);
                    bulk_g2s(smem_u32(dynbuf + s * STAGE_F), src, bytes, fb);
                }
            }
        }
    } else {
        // ===== consumer warp w: owns stage w; its k-th tile is l = k*7 + w =====
        const int gid = lane >> 3;     // 8-lane group (token slot 0..3)
        const int sub = lane & 7;      // d-quarter within token
        float* const srow = scores[w];
        const uint32_t fb = smem_u32(&full_b[w]);
        const uint32_t eb = smem_u32(&empty_b[w]);
        const float*  buf = dynbuf + w * STAGE_F;
        const float4* t4  = reinterpret_cast<const float4*>(buf);

        for (int k = 0; ; k++) {
            const int l = k * NCONS + w;
            if (l >= n) break;

            mbar_wait(fb, (uint32_t)(k & 1));

            const int id = start + l;
            const int b  = id >> 6;
            const int g  = id & 63;
            const int gm = id & 3;
            const int nt = (gm + 1) << 4;

            // s_i chunks for this lane's 4 column-quarters (L2-resident)
            const float4* const s4p =
                reinterpret_cast<const float4*>(s_i + (size_t)b * D0);
            const float4 s0 = __ldg(s4p + sub);
            const float4 s1 = __ldg(s4p + sub + 8);
            const float4 s2 = __ldg(s4p + sub + 16);
            const float4 s3 = __ldg(s4p + sub + 24);

            // ---- phase A: scores; 4 tokens per pass, 8 lanes per token ----
            #pragma unroll 4
            for (int tk = gid; tk < nt; tk += 4) {
                const float4 v0 = t4[tk * 32 + sub];
                const float4 v1 = t4[tk * 32 + sub + 8];
                const float4 v2 = t4[tk * 32 + sub + 16];
                const float4 v3 = t4[tk * 32 + sub + 24];
                float x = v0.x*s0.x + v0.y*s0.y + v0.z*s0.z + v0.w*s0.w
                        + v1.x*s1.x + v1.y*s1.y + v1.z*s1.z + v1.w*s1.w
                        + v2.x*s2.x + v2.y*s2.y + v2.z*s2.z + v2.w*s2.w
                        + v3.x*s3.x + v3.y*s3.y + v3.z*s3.z + v3.w*s3.w;
                x += __shfl_xor_sync(0xffffffffu, x, 4);
                x += __shfl_xor_sync(0xffffffffu, x, 2);
                x += __shfl_xor_sync(0xffffffffu, x, 1);
                if (sub == 0) srow[tk] = x * (1.0f / 128.0f);   // / d0
            }
            __syncwarp();

            // ---- phase B: in-warp softmax; weights stay in registers ----
            const float a0 = (lane      < nt) ? srow[lane]      : -3.4e38f;
            const float a1 = (lane + 32 < nt) ? srow[lane + 32] : -3.4e38f;
            float m = fmaxf(a0, a1);
            #pragma unroll
            for (int o = 16; o > 0; o >>= 1)
                m = fmaxf(m, __shfl_xor_sync(0xffffffffu, m, o));
            const float e0 = (lane      < nt) ? __expf(a0 - m) : 0.0f;
            const float e1 = (lane + 32 < nt) ? __expf(a1 - m) : 0.0f;
            float sd = e0 + e1;
            #pragma unroll
            for (int o = 16; o > 0; o >>= 1)
                sd += __shfl_xor_sync(0xffffffffu, sd, o);
            const float inv = 1.0f / sd;
            const float wl = e0 * inv;     // weight of token 'lane'
            const float wh = e1 * inv;     // weight of token 'lane+32'

            // ---- phase C: weighted sum; weights broadcast via shuffle ----
            float4 acc = make_float4(0.f, 0.f, 0.f, 0.f);
            for (int t = 0; t < nt; t += 4) {
                const float base = (t < 32) ? wl : wh;     // uniform select
                const float w0 = __shfl_sync(0xffffffffu, base, (t + 0) & 31);
                const float w1 = __shfl_sync(0xffffffffu, base, (t + 1) & 31);
                const float w2 = __shfl_sync(0xffffffffu, base, (t + 2) & 31);
                const float w3 = __shfl_sync(0xffffffffu, base, (t + 3) & 31);
                const float4 va = t4[(t + 0) * 32 + lane];
                const float4 vb = t4[(t + 1) * 32 + lane];
                const float4 vc = t4[(t + 2) * 32 + lane];
                const float4 vd = t4[(t + 3) * 32 + lane];
                acc.x += w0*va.x + w1*vb.x + w2*vc.x + w3*vd.x;
                acc.y += w0*va.y + w1*vb.y + w2*vc.y + w3*vd.y;
                acc.z += w0*va.z + w1*vb.z + w2*vc.z + w3*vd.z;
                acc.w += w0*va.w + w1*vb.w + w2*vc.w + w3*vd.w;
            }
            reinterpret_cast<float4*>(out + ((size_t)b * NGRP + g) * D0)[lane] = acc;

            __syncwarp();                      // all lanes done reading buf
            if (lane == 0) mbar_arrive(eb);    // stage free for next fill
        }
    }
}

extern "C" void kernel_launch(void* const* d_in, const int* in_sizes, int n_in,
                              void* d_out, int out_size)
{
    const float* s_i   = (const float*)d_in[0];   // [256,128]
    const float* theta = (const float*)d_in[1];   // [256,2560,128]
    float* out = (float*)d_out;                   // [256,64,128]
    (void)in_sizes; (void)n_in; (void)out_size;

    const size_t dyn = (size_t)NCONS * STAGE_F * sizeof(float);   // 224 KB
    cudaFuncSetAttribute(ragged_attn_ws2,
                         cudaFuncAttributeMaxDynamicSharedMemorySize, (int)dyn);
    ragged_attn_ws2<<<GRID, THREADS, dyn>>>(s_i, theta, out);
}

// round 7
// speedup vs baseline: 1.3398x; 1.0071x over previous
#include <cuda_runtime.h>
#include <cstdint>
#include <cstddef>

#define D0      128
#define NGRP    64
#define NB      256
#define TTOT    2560
#define NTILES  (NB * NGRP)     // 16384
#define NQUADS  (NTILES / 4)    // 4096
#define GRID    152             // 1 CTA per SM
#define THREADS 256             // warps 0..6 consumers, warp 7 producer
#define NCONS   7
#define STAGE_F (64 * D0)       // floats per stage (max tile 64x128 = 32 KB)
#define NSPLIT  4               // bulk copies per tile (concurrency lever)

// ---------------- PTX helpers ----------------
__device__ __forceinline__ uint32_t smem_u32(const void* p) {
    return (uint32_t)__cvta_generic_to_shared(p);
}
__device__ __forceinline__ void mbar_init(uint32_t mbar, uint32_t cnt) {
    asm volatile("mbarrier.init.shared.b64 [%0], %1;" :: "r"(mbar), "r"(cnt) : "memory");
}
__device__ __forceinline__ void mbar_expect_tx(uint32_t mbar, uint32_t bytes) {
    asm volatile("mbarrier.arrive.expect_tx.shared.b64 _, [%0], %1;"
                 :: "r"(mbar), "r"(bytes) : "memory");
}
__device__ __forceinline__ void mbar_arrive(uint32_t mbar) {
    asm volatile("mbarrier.arrive.shared.b64 _, [%0];" :: "r"(mbar) : "memory");
}
__device__ __forceinline__ void bulk_g2s(uint32_t dst, const void* src,
                                         uint32_t bytes, uint32_t mbar) {
    asm volatile("cp.async.bulk.shared::cluster.global.mbarrier::complete_tx::bytes "
                 "[%0], [%1], %2, [%3];"
                 :: "r"(dst), "l"(src), "r"(bytes), "r"(mbar) : "memory");
}
// blocks until the phase with the given parity has completed
__device__ __forceinline__ void mbar_wait(uint32_t mbar, uint32_t parity) {
    asm volatile(
        "{\n\t.reg .pred P;\n"
        "WL%=:\n\t"
        "mbarrier.try_wait.parity.acquire.cta.shared::cta.b64 P, [%0], %1, 0x989680;\n\t"
        "@P bra WD%=;\n\t"
        "bra WL%=;\n"
        "WD%=:\n\t}"
        :: "r"(mbar), "r"(parity) : "memory");
}
__device__ __forceinline__ void fence_async() {
    asm volatile("fence.proxy.async.shared::cta;" ::: "memory");
}

extern __shared__ float dynbuf[];   // NCONS * 32 KB = 224 KB

__global__ __launch_bounds__(THREADS, 1)
void ragged_attn_ws3(const float* __restrict__ s_i,
                     const float* __restrict__ theta,
                     float* __restrict__ out)
{
    __shared__ __align__(8)  unsigned long long full_b[NCONS];
    __shared__ __align__(8)  unsigned long long empty_b[NCONS];
    __shared__ __align__(16) float scores[NCONS][64];   // scalar access only

    const int tid  = threadIdx.x;
    const int lane = tid & 31;
    const int w    = tid >> 5;

    // tile range for this CTA, aligned to the 4-tile size cycle
    const int qs    = (int)(((long long)blockIdx.x       * NQUADS) / GRID);
    const int qe    = (int)(((long long)(blockIdx.x + 1) * NQUADS) / GRID);
    const int start = qs * 4;
    const int n     = (qe - qs) * 4;

    if (tid == 0) {
        #pragma unroll
        for (int s = 0; s < NCONS; s++) {
            mbar_init(smem_u32(&full_b[s]), 1);
            mbar_init(smem_u32(&empty_b[s]), 1);
        }
    }
    __syncthreads();   // the only block barrier

    if (w == NCONS) {
        // ===== producer: warp 7 lane 0, fills stage s with tiles l = r*7+s =====
        if (lane == 0) {
            int l = 0;
            for (int r = 0; l < n; r++) {
                const uint32_t ewait = (r & 1) ^ 1;   // r=0 passes on fresh barrier
                for (int s = 0; s < NCONS && l < n; s++, l++) {
                    mbar_wait(smem_u32(&empty_b[s]), ewait);

                    const int id = start + l;
                    const int gm = id & 3;
                    const int nt = (gm + 1) << 4;
                    const int g  = id & 63;
                    const int t0 = (g >> 2) * 160 + gm * (gm + 1) * 8;
                    const char* src = (const char*)
                        (theta + ((size_t)(id >> 6) * TTOT + t0) * D0);
                    const uint32_t bytes  = (uint32_t)nt * D0 * 4u;
                    const uint32_t qbytes = bytes / NSPLIT;     // 2..8 KB
                    const uint32_t fb  = smem_u32(&full_b[s]);
                    const uint32_t dst = smem_u32(dynbuf + s * STAGE_F);

                    fence_async();
                    mbar_expect_tx(fb, bytes);
                    #pragma unroll
                    for (int p = 0; p < NSPLIT; p++)
                        bulk_g2s(dst + p * qbytes, src + p * qbytes, qbytes, fb);
                }
            }
        }
    } else {
        // ===== consumer warp w: owns stage w; its k-th tile is l = k*7 + w =====
        const int gid = lane >> 3;     // 8-lane group (token slot 0..3)
        const int sub = lane & 7;      // d-quarter within token
        float* const srow = scores[w];
        const uint32_t fb = smem_u32(&full_b[w]);
        const uint32_t eb = smem_u32(&empty_b[w]);
        const float*  buf = dynbuf + w * STAGE_F;
        const float4* t4  = reinterpret_cast<const float4*>(buf);

        for (int k = 0; ; k++) {
            const int l = k * NCONS + w;
            if (l >= n) break;

            mbar_wait(fb, (uint32_t)(k & 1));

            const int id = start + l;
            const int b  = id >> 6;
            const int g  = id & 63;
            const int gm = id & 3;
            const int nt = (gm + 1) << 4;

            // s_i chunks for this lane's 4 column-quarters (L2-resident)
            const float4* const s4p =
                reinterpret_cast<const float4*>(s_i + (size_t)b * D0);
            const float4 s0 = __ldg(s4p + sub);
            const float4 s1 = __ldg(s4p + sub + 8);
            const float4 s2 = __ldg(s4p + sub + 16);
            const float4 s3 = __ldg(s4p + sub + 24);

            // ---- phase A: scores; 4 tokens per pass, 8 lanes per token ----
            #pragma unroll 4
            for (int tk = gid; tk < nt; tk += 4) {
                const float4 v0 = t4[tk * 32 + sub];
                const float4 v1 = t4[tk * 32 + sub + 8];
                const float4 v2 = t4[tk * 32 + sub + 16];
                const float4 v3 = t4[tk * 32 + sub + 24];
                float x = v0.x*s0.x + v0.y*s0.y + v0.z*s0.z + v0.w*s0.w
                        + v1.x*s1.x + v1.y*s1.y + v1.z*s1.z + v1.w*s1.w
                        + v2.x*s2.x + v2.y*s2.y + v2.z*s2.z + v2.w*s2.w
                        + v3.x*s3.x + v3.y*s3.y + v3.z*s3.z + v3.w*s3.w;
                x += __shfl_xor_sync(0xffffffffu, x, 4);
                x += __shfl_xor_sync(0xffffffffu, x, 2);
                x += __shfl_xor_sync(0xffffffffu, x, 1);
                if (sub == 0) srow[tk] = x * (1.0f / 128.0f);   // / d0
            }
            __syncwarp();

            // ---- phase B: in-warp softmax; weights stay in registers ----
            const float a0 = (lane      < nt) ? srow[lane]      : -3.4e38f;
            const float a1 = (lane + 32 < nt) ? srow[lane + 32] : -3.4e38f;
            float m = fmaxf(a0, a1);
            #pragma unroll
            for (int o = 16; o > 0; o >>= 1)
                m = fmaxf(m, __shfl_xor_sync(0xffffffffu, m, o));
            const float e0 = (lane      < nt) ? __expf(a0 - m) : 0.0f;
            const float e1 = (lane + 32 < nt) ? __expf(a1 - m) : 0.0f;
            float sd = e0 + e1;
            #pragma unroll
            for (int o = 16; o > 0; o >>= 1)
                sd += __shfl_xor_sync(0xffffffffu, sd, o);
            const float inv = 1.0f / sd;
            const float wl = e0 * inv;     // weight of token 'lane'
            const float wh = e1 * inv;     // weight of token 'lane+32'

            // ---- phase C: weighted sum; weights broadcast via shuffle ----
            float4 acc = make_float4(0.f, 0.f, 0.f, 0.f);
            for (int t = 0; t < nt; t += 4) {
                const float base = (t < 32) ? wl : wh;     // uniform select
                const float w0 = __shfl_sync(0xffffffffu, base, (t + 0) & 31);
                const float w1 = __shfl_sync(0xffffffffu, base, (t + 1) & 31);
                const float w2 = __shfl_sync(0xffffffffu, base, (t + 2) & 31);
                const float w3 = __shfl_sync(0xffffffffu, base, (t + 3) & 31);
                const float4 va = t4[(t + 0) * 32 + lane];
                const float4 vb = t4[(t + 1) * 32 + lane];
                const float4 vc = t4[(t + 2) * 32 + lane];
                const float4 vd = t4[(t + 3) * 32 + lane];
                acc.x += w0*va.x + w1*vb.x + w2*vc.x + w3*vd.x;
                acc.y += w0*va.y + w1*vb.y + w2*vc.y + w3*vd.y;
                acc.z += w0*va.z + w1*vb.z + w2*vc.z + w3*vd.z;
                acc.w += w0*va.w + w1*vb.w + w2*vc.w + w3*vd.w;
            }
            reinterpret_cast<float4*>(out + ((size_t)b * NGRP + g) * D0)[lane] = acc;

            __syncwarp();                      // all lanes done reading buf
            if (lane == 0) mbar_arrive(eb);    // stage free for next fill
        }
    }
}

extern "C" void kernel_launch(void* const* d_in, const int* in_sizes, int n_in,
                              void* d_out, int out_size)
{
    const float* s_i   = (const float*)d_in[0];   // [256,128]
    const float* theta = (const float*)d_in[1];   // [256,2560,128]
    float* out = (float*)d_out;                   // [256,64,128]
    (void)in_sizes; (void)n_in; (void)out_size;

    const size_t dyn = (size_t)NCONS * STAGE_F * sizeof(float);   // 224 KB
    cudaFuncSetAttribute(ragged_attn_ws3,
                         cudaFuncAttributeMaxDynamicSharedMemorySize, (int)dyn);
    ragged_attn_ws3<<<GRID, THREADS, dyn>>>(s_i, theta, out);
}

// round 8
// speedup vs baseline: 1.4162x; 1.0570x over previous
#include <cuda_runtime.h>
#include <cstdint>
#include <cstddef>

#define D0      128
#define NGRP    64
#define NB      256
#define TTOT    2560
#define NTILES  (NB * NGRP)     // 16384
#define NQUADS  (NTILES / 4)    // 4096
#define GRID    152             // 1 CTA per SM
#define THREADS 256             // warps 0..6 consumers, warp 7 producer
#define NCONS   7
#define STAGE_F (64 * D0)       // floats per stage (max tile 64x128 = 32 KB)
#define NSPLIT  4               // bulk copies per tile

// ---------------- PTX helpers ----------------
__device__ __forceinline__ uint32_t smem_u32(const void* p) {
    return (uint32_t)__cvta_generic_to_shared(p);
}
__device__ __forceinline__ void mbar_init(uint32_t mbar, uint32_t cnt) {
    asm volatile("mbarrier.init.shared.b64 [%0], %1;" :: "r"(mbar), "r"(cnt) : "memory");
}
__device__ __forceinline__ void mbar_expect_tx(uint32_t mbar, uint32_t bytes) {
    asm volatile("mbarrier.arrive.expect_tx.shared.b64 _, [%0], %1;"
                 :: "r"(mbar), "r"(bytes) : "memory");
}
__device__ __forceinline__ void mbar_arrive(uint32_t mbar) {
    asm volatile("mbarrier.arrive.shared.b64 _, [%0];" :: "r"(mbar) : "memory");
}
__device__ __forceinline__ void bulk_g2s(uint32_t dst, const void* src,
                                         uint32_t bytes, uint32_t mbar) {
    asm volatile("cp.async.bulk.shared::cluster.global.mbarrier::complete_tx::bytes "
                 "[%0], [%1], %2, [%3];"
                 :: "r"(dst), "l"(src), "r"(bytes), "r"(mbar) : "memory");
}
// blocks until the phase with the given parity has completed
__device__ __forceinline__ void mbar_wait(uint32_t mbar, uint32_t parity) {
    asm volatile(
        "{\n\t.reg .pred P;\n"
        "WL%=:\n\t"
        "mbarrier.try_wait.parity.acquire.cta.shared::cta.b64 P, [%0], %1, 0x989680;\n\t"
        "@P bra WD%=;\n\t"
        "bra WL%=;\n"
        "WD%=:\n\t}"
        :: "r"(mbar), "r"(parity) : "memory");
}
__device__ __forceinline__ void fence_async() {
    asm volatile("fence.proxy.async.shared::cta;" ::: "memory");
}

extern __shared__ float dynbuf[];   // NCONS * 32 KB = 224 KB

__global__ __launch_bounds__(THREADS, 1)
void ragged_attn_ws4(const float* __restrict__ s_i,
                     const float* __restrict__ theta,
                     float* __restrict__ out)
{
    __shared__ __align__(8)  unsigned long long full_b[NCONS];
    __shared__ __align__(8)  unsigned long long empty_b[NCONS];
    __shared__ __align__(16) float scores[NCONS][64];   // scalar access only

    const int tid  = threadIdx.x;
    const int lane = tid & 31;
    const int w    = tid >> 5;

    // tile range for this CTA, aligned to the 4-tile size cycle
    const int qs    = (int)(((long long)blockIdx.x       * NQUADS) / GRID);
    const int qe    = (int)(((long long)(blockIdx.x + 1) * NQUADS) / GRID);
    const int start = qs * 4;
    const int n     = (qe - qs) * 4;

    if (tid == 0) {
        #pragma unroll
        for (int s = 0; s < NCONS; s++) {
            mbar_init(smem_u32(&full_b[s]), 1);
            mbar_init(smem_u32(&empty_b[s]), 1);
        }
    }
    __syncthreads();   // the only block barrier

    if (w == NCONS) {
        // ===== producer warp: lane s (<7) independently services stage s =====
        const int s = lane;
        if (s < NCONS) {
            const uint32_t fb  = smem_u32(&full_b[s]);
            const uint32_t eb  = smem_u32(&empty_b[s]);
            const uint32_t dst = smem_u32(dynbuf + s * STAGE_F);

            for (int k = 0; ; k++) {
                const int l = k * NCONS + s;
                if (l >= n) break;

                // k-th refill: wait until consumer freed fill k-1
                mbar_wait(eb, ((uint32_t)k & 1u) ^ 1u);

                const int id = start + l;
                const int gm = id & 3;
                const int nt = (gm + 1) << 4;
                const int g  = id & 63;
                const int t0 = (g >> 2) * 160 + gm * (gm + 1) * 8;
                const char* src = (const char*)
                    (theta + ((size_t)(id >> 6) * TTOT + t0) * D0);
                const uint32_t bytes  = (uint32_t)nt * D0 * 4u;
                const uint32_t qbytes = bytes / NSPLIT;     // 2..8 KB

                fence_async();
                mbar_expect_tx(fb, bytes);
                #pragma unroll
                for (int p = 0; p < NSPLIT; p++)
                    bulk_g2s(dst + p * qbytes, src + p * qbytes, qbytes, fb);
            }
        }
    } else {
        // ===== consumer warp w: owns stage w; its k-th tile is l = k*7 + w =====
        const int gid = lane >> 3;     // 8-lane group (token slot 0..3)
        const int sub = lane & 7;      // d-quarter within token
        float* const srow = scores[w];
        const uint32_t fb = smem_u32(&full_b[w]);
        const uint32_t eb = smem_u32(&empty_b[w]);
        const float*  buf = dynbuf + w * STAGE_F;
        const float4* t4  = reinterpret_cast<const float4*>(buf);

        for (int k = 0; ; k++) {
            const int l = k * NCONS + w;
            if (l >= n) break;

            mbar_wait(fb, (uint32_t)(k & 1));

            const int id = start + l;
            const int b  = id >> 6;
            const int g  = id & 63;
            const int gm = id & 3;
            const int nt = (gm + 1) << 4;

            // s_i chunks for this lane's 4 column-quarters (L2-resident)
            const float4* const s4p =
                reinterpret_cast<const float4*>(s_i + (size_t)b * D0);
            const float4 s0 = __ldg(s4p + sub);
            const float4 s1 = __ldg(s4p + sub + 8);
            const float4 s2 = __ldg(s4p + sub + 16);
            const float4 s3 = __ldg(s4p + sub + 24);

            // ---- phase A: scores; 4 tokens per pass, 8 lanes per token ----
            #pragma unroll 4
            for (int tk = gid; tk < nt; tk += 4) {
                const float4 v0 = t4[tk * 32 + sub];
                const float4 v1 = t4[tk * 32 + sub + 8];
                const float4 v2 = t4[tk * 32 + sub + 16];
                const float4 v3 = t4[tk * 32 + sub + 24];
                float x = v0.x*s0.x + v0.y*s0.y + v0.z*s0.z + v0.w*s0.w
                        + v1.x*s1.x + v1.y*s1.y + v1.z*s1.z + v1.w*s1.w
                        + v2.x*s2.x + v2.y*s2.y + v2.z*s2.z + v2.w*s2.w
                        + v3.x*s3.x + v3.y*s3.y + v3.z*s3.z + v3.w*s3.w;
                x += __shfl_xor_sync(0xffffffffu, x, 4);
                x += __shfl_xor_sync(0xffffffffu, x, 2);
                x += __shfl_xor_sync(0xffffffffu, x, 1);
                if (sub == 0) srow[tk] = x * (1.0f / 128.0f);   // / d0
            }
            __syncwarp();

            // ---- phase B: in-warp softmax; weights stay in registers ----
            const float a0 = (lane      < nt) ? srow[lane]      : -3.4e38f;
            const float a1 = (lane + 32 < nt) ? srow[lane + 32] : -3.4e38f;
            float m = fmaxf(a0, a1);
            #pragma unroll
            for (int o = 16; o > 0; o >>= 1)
                m = fmaxf(m, __shfl_xor_sync(0xffffffffu, m, o));
            const float e0 = (lane      < nt) ? __expf(a0 - m) : 0.0f;
            const float e1 = (lane + 32 < nt) ? __expf(a1 - m) : 0.0f;
            float sd = e0 + e1;
            #pragma unroll
            for (int o = 16; o > 0; o >>= 1)
                sd += __shfl_xor_sync(0xffffffffu, sd, o);
            const float inv = 1.0f / sd;
            const float wl = e0 * inv;     // weight of token 'lane'
            const float wh = e1 * inv;     // weight of token 'lane+32'

            // ---- phase C: weighted sum; weights broadcast via shuffle ----
            float4 acc = make_float4(0.f, 0.f, 0.f, 0.f);
            for (int t = 0; t < nt; t += 4) {
                const float base = (t < 32) ? wl : wh;     // uniform select
                const float w0 = __shfl_sync(0xffffffffu, base, (t + 0) & 31);
                const float w1 = __shfl_sync(0xffffffffu, base, (t + 1) & 31);
                const float w2 = __shfl_sync(0xffffffffu, base, (t + 2) & 31);
                const float w3 = __shfl_sync(0xffffffffu, base, (t + 3) & 31);
                const float4 va = t4[(t + 0) * 32 + lane];
                const float4 vb = t4[(t + 1) * 32 + lane];
                const float4 vc = t4[(t + 2) * 32 + lane];
                const float4 vd = t4[(t + 3) * 32 + lane];
                acc.x += w0*va.x + w1*vb.x + w2*vc.x + w3*vd.x;
                acc.y += w0*va.y + w1*vb.y + w2*vc.y + w3*vd.y;
                acc.z += w0*va.z + w1*vb.z + w2*vc.z + w3*vd.z;
                acc.w += w0*va.w + w1*vb.w + w2*vc.w + w3*vd.w;
            }
            reinterpret_cast<float4*>(out + ((size_t)b * NGRP + g) * D0)[lane] = acc;

            __syncwarp();                      // all lanes done reading buf
            if (lane == 0) mbar_arrive(eb);    // stage free for next fill
        }
    }
}

extern "C" void kernel_launch(void* const* d_in, const int* in_sizes, int n_in,
                              void* d_out, int out_size)
{
    const float* s_i   = (const float*)d_in[0];   // [256,128]
    const float* theta = (const float*)d_in[1];   // [256,2560,128]
    float* out = (float*)d_out;                   // [256,64,128]
    (void)in_sizes; (void)n_in; (void)out_size;

    const size_t dyn = (size_t)NCONS * STAGE_F * sizeof(float);   // 224 KB
    cudaFuncSetAttribute(ragged_attn_ws4,
                         cudaFuncAttributeMaxDynamicSharedMemorySize, (int)dyn);
    ragged_attn_ws4<<<GRID, THREADS, dyn>>>(s_i, theta, out);
}